// round 6
// baseline (speedup 1.0000x reference)
#include <cuda_runtime.h>
#include <math.h>

#define H 160           // B*G = 4*40 heads
#define C 13
#define T 1024
#define F 513           // rfft bins
#define NSIG (H * C)    // 2080 signals

typedef unsigned long long ull;

// ---------------- f32x2 packed math helpers (sm_103a FFMA2) ----------------
__device__ __forceinline__ ull pk2(float a, float b) {
    ull r;
    asm("mov.b64 %0, {%1, %2};" : "=l"(r) : "r"(__float_as_uint(a)), "r"(__float_as_uint(b)));
    return r;
}
__device__ __forceinline__ void upk2(ull v, float& a, float& b) {
    unsigned lo, hi;
    asm("mov.b64 {%0, %1}, %2;" : "=r"(lo), "=r"(hi) : "l"(v));
    a = __uint_as_float(lo);
    b = __uint_as_float(hi);
}
__device__ __forceinline__ ull fma2(ull a, ull b, ull c) {
    ull d;
    asm("fma.rn.f32x2 %0, %1, %2, %3;" : "=l"(d) : "l"(a), "l"(b), "l"(c));
    return d;
}

// ---------------- scratch (device globals: allowed; no runtime alloc) ------
__device__ float2 d_W[512];        // twiddles exp(-2*pi*i*k/1024)
__device__ float2 d_X[H * C * F];  // spectrum, layout [head][c][f]
__device__ float2 d_Q[H * C * F];
__device__ float2 d_K[H * C * F];
__device__ float2 d_V[H * C * F];
__device__ float2 d_O[H * C * F];

// ---------------- twiddle init (double trig for precision) -----------------
__global__ void init_twiddles() {
    int k = threadIdx.x;  // 0..511
    double ang = -2.0 * 3.14159265358979323846 * (double)k / 1024.0;
    d_W[k] = make_float2((float)cos(ang), (float)sin(ang));
}

// ---------------- shared radix-2 DIT FFT core (1024 pts, 512 threads) ------
__device__ __forceinline__ void fft_stages(float2* a, bool inverse) {
    int tid = threadIdx.x;
#pragma unroll
    for (int s = 1; s <= 10; ++s) {
        __syncthreads();
        int half = 1 << (s - 1);
        int k = tid & (half - 1);
        int i0 = ((tid >> (s - 1)) << s) + k;
        float2 w = d_W[k << (10 - s)];
        if (inverse) w.y = -w.y;
        float2 u = a[i0];
        float2 v = a[i0 + half];
        float tr = w.x * v.x - w.y * v.y;
        float ti = w.x * v.y + w.y * v.x;
        a[i0]        = make_float2(u.x + tr, u.y + ti);
        a[i0 + half] = make_float2(u.x - tr, u.y - ti);
    }
    __syncthreads();
}

// ---------------- forward rfft: x[sig][0..1023] -> d_X[sig][0..512] --------
__global__ void fft_forward(const float* __restrict__ x) {
    __shared__ float2 a[1024];
    int sig = blockIdx.x;   // head*13 + c
    int tid = threadIdx.x;  // 0..511
    const float* xp = x + sig * 1024;
    a[__brev(tid) >> 22]       = make_float2(xp[tid], 0.f);
    a[__brev(tid + 512) >> 22] = make_float2(xp[tid + 512], 0.f);
    fft_stages(a, false);
    float2* Xp = d_X + sig * F;
    Xp[tid] = a[tid];
    if (tid == 0) Xp[512] = a[512];
}

// ---------------- QKV: [head][c][f] = sum_cin X[head][cin][f] * W[cin][c] --
__global__ void qkv_kernel(const float* __restrict__ wq,
                           const float* __restrict__ wk,
                           const float* __restrict__ wv) {
    __shared__ float ws[3][169];
    int tid = threadIdx.x;
    if (tid < 169) {
        ws[0][tid] = wq[tid];
        ws[1][tid] = wk[tid];
        ws[2][tid] = wv[tid];
    }
    __syncthreads();
    int head = blockIdx.y;
    int f = blockIdx.x * blockDim.x + tid;
    if (f >= F) return;
    float xr[13], xi[13];
#pragma unroll
    for (int c = 0; c < 13; ++c) {
        float2 v = d_X[(head * 13 + c) * F + f];
        xr[c] = v.x;
        xi[c] = v.y;
    }
#pragma unroll 1
    for (int co = 0; co < 13; ++co) {
        float qr = 0.f, qi = 0.f, kr = 0.f, ki = 0.f, vr = 0.f, vi = 0.f;
#pragma unroll
        for (int ci = 0; ci < 13; ++ci) {
            float a = ws[0][ci * 13 + co];
            qr = fmaf(xr[ci], a, qr); qi = fmaf(xi[ci], a, qi);
            float b = ws[1][ci * 13 + co];
            kr = fmaf(xr[ci], b, kr); ki = fmaf(xi[ci], b, ki);
            float g = ws[2][ci * 13 + co];
            vr = fmaf(xr[ci], g, vr); vi = fmaf(xi[ci], g, vi);
        }
        int o = (head * 13 + co) * F + f;
        d_Q[o] = make_float2(qr, qi);
        d_K[o] = make_float2(kr, ki);
        d_V[o] = make_float2(vr, vi);
    }
}

// ---------------- attention ------------------------------------------------
// 256 threads = 8 warps; each warp owns a ROW PAIR (2 query rows), packed
// into f32x2 registers. Pass 1 uses FFMA2 (4 FMA2 + 4 dup-MOV per c vs 8
// scalar FFMA) spreading work across fma+alu pipes. Scores stored packed
// {row0,row1} so softmax + pass 2 read single LDS.64. Pass 2 scalar (dup
// cost there exceeds FMA savings).
#define TR 16
#define KT 128
#define NTILE 5

__global__ __launch_bounds__(256, 3) void attn_kernel() {
    __shared__ float2 s_sm[8 * F];       // packed scores per warp-row-pair: 32832 B
    __shared__ float2 kv_sm[13 * KT];    // 13312 B   (total 46144 B)

    int head = blockIdx.y;
    int tid = threadIdx.x, lane = tid & 31, w = tid >> 5;  // w = 0..7
    int f0 = blockIdx.x * TR + 2 * w;
    int f1 = f0 + 1;
    bool act0 = f0 < F, act1 = f1 < F;

    // Q row pair -> packed registers (warp-uniform broadcast loads)
    ull qx[13], qy[13];
#pragma unroll
    for (int c = 0; c < 13; ++c) {
        float2 a = act0 ? d_Q[(head * 13 + c) * F + f0] : make_float2(0.f, 0.f);
        float2 b = act1 ? d_Q[(head * 13 + c) * F + f1] : make_float2(0.f, 0.f);
        qx[c] = pk2(a.x, b.x);
        qy[c] = pk2(a.y, b.y);
    }

    // pass 1: scores = |q . conj? no: q . k with complex mul| ; sr = A - B
    float m0 = 0.f, m1 = 0.f;  // scores are non-negative
    const ull Z = pk2(0.f, 0.f);
    for (int tile = 0; tile < NTILE; ++tile) {
        int base = tile * KT;
        __syncthreads();
        for (int i = tid; i < 13 * KT; i += 256) {
            int c = i >> 7, fl = i & 127;
            int f2 = base + fl;
            kv_sm[c * KT + fl] = (f2 < F) ? d_K[(head * 13 + c) * F + f2] : make_float2(0.f, 0.f);
        }
        __syncthreads();
#pragma unroll
        for (int j = 0; j < 4; ++j) {
            int fl = j * 32 + lane;
            int f2 = base + fl;
            ull A = Z, B = Z, S = Z;
#pragma unroll
            for (int c = 0; c < 13; ++c) {
                float2 k = kv_sm[c * KT + fl];
                ull kxx = pk2(k.x, k.x);
                ull kyy = pk2(k.y, k.y);
                A = fma2(qx[c], kxx, A);   // += qx*kx   (-> sr pos part)
                B = fma2(qy[c], kyy, B);   // += qy*ky   (-> sr neg part)
                S = fma2(qx[c], kyy, S);   // += qx*ky   (-> si)
                S = fma2(qy[c], kxx, S);   // += qy*kx
            }
            float a0, a1, b0, b1, s0, s1;
            upk2(A, a0, a1); upk2(B, b0, b1); upk2(S, s0, s1);
            float sr0 = a0 - b0, sr1 = a1 - b1;
            float n0 = fmaf(sr0, sr0, s0 * s0);
            float n1 = fmaf(sr1, sr1, s1 * s1);
            float sc0 = n0 > 0.f ? n0 * __frsqrt_rn(n0) : 0.f;
            float sc1 = n1 > 0.f ? n1 * __frsqrt_rn(n1) : 0.f;
            m0 = fmaxf(m0, sc0);
            m1 = fmaxf(m1, sc1);
            if (f2 < F) s_sm[w * F + f2] = make_float2(sc0, sc1);
        }
    }

    // row-pair softmax (per warp)
#pragma unroll
    for (int o = 16; o; o >>= 1) {
        m0 = fmaxf(m0, __shfl_xor_sync(0xffffffffu, m0, o));
        m1 = fmaxf(m1, __shfl_xor_sync(0xffffffffu, m1, o));
    }
    float l0 = 0.f, l1 = 0.f;
    for (int f2 = lane; f2 < F; f2 += 32) {
        float2 s = s_sm[w * F + f2];
        float p0 = __expf(s.x - m0);
        float p1 = __expf(s.y - m1);
        s_sm[w * F + f2] = make_float2(p0, p1);
        l0 += p0;
        l1 += p1;
    }
#pragma unroll
    for (int o = 16; o; o >>= 1) {
        l0 += __shfl_xor_sync(0xffffffffu, l0, o);
        l1 += __shfl_xor_sync(0xffffffffu, l1, o);
    }
    float inv0 = 1.f / l0, inv1 = 1.f / l1;

    // pass 2: out = P @ V (scalar; one V load serves both rows)
    float ar0[13], ai0[13], ar1[13], ai1[13];
#pragma unroll
    for (int c = 0; c < 13; ++c) { ar0[c] = ai0[c] = ar1[c] = ai1[c] = 0.f; }
    for (int tile = 0; tile < NTILE; ++tile) {
        int base = tile * KT;
        __syncthreads();
        for (int i = tid; i < 13 * KT; i += 256) {
            int c = i >> 7, fl = i & 127;
            int f2 = base + fl;
            kv_sm[c * KT + fl] = (f2 < F) ? d_V[(head * 13 + c) * F + f2] : make_float2(0.f, 0.f);
        }
        __syncthreads();
#pragma unroll
        for (int j = 0; j < 4; ++j) {
            int fl = j * 32 + lane;
            int f2 = base + fl;
            float2 p = (f2 < F) ? s_sm[w * F + f2] : make_float2(0.f, 0.f);
#pragma unroll
            for (int c = 0; c < 13; ++c) {
                float2 v = kv_sm[c * KT + fl];
                ar0[c] = fmaf(p.x, v.x, ar0[c]);
                ai0[c] = fmaf(p.x, v.y, ai0[c]);
                ar1[c] = fmaf(p.y, v.x, ar1[c]);
                ai1[c] = fmaf(p.y, v.y, ai1[c]);
            }
        }
    }

    // warp-reduce accumulators, lane 0 writes
#pragma unroll
    for (int c = 0; c < 13; ++c) {
#pragma unroll
        for (int o = 16; o; o >>= 1) {
            ar0[c] += __shfl_xor_sync(0xffffffffu, ar0[c], o);
            ai0[c] += __shfl_xor_sync(0xffffffffu, ai0[c], o);
            ar1[c] += __shfl_xor_sync(0xffffffffu, ar1[c], o);
            ai1[c] += __shfl_xor_sync(0xffffffffu, ai1[c], o);
        }
    }
    if (lane == 0) {
#pragma unroll
        for (int c = 0; c < 13; ++c) {
            if (act0) d_O[(head * 13 + c) * F + f0] = make_float2(ar0[c] * inv0, ai0[c] * inv0);
            if (act1) d_O[(head * 13 + c) * F + f1] = make_float2(ar1[c] * inv1, ai1[c] * inv1);
        }
    }
}

// ---------------- irfft: Hermitian extend + inverse FFT, real part ---------
__global__ void ifft_kernel(float* __restrict__ out) {
    __shared__ float2 a[1024];
    int sig = blockIdx.x;
    int tid = threadIdx.x;  // 0..511
    const float2* Op = d_O + sig * F;
    float2 o = Op[tid];
    a[__brev(tid) >> 22] = o;
    if (tid > 0) a[__brev(1024 - tid) >> 22] = make_float2(o.x, -o.y);
    if (tid == 0) a[__brev(512) >> 22] = Op[512];
    fft_stages(a, true);
    const float scale = 1.0f / 1024.0f;
    float* op = out + sig * 1024;
    op[tid]       = a[tid].x * scale;
    op[tid + 512] = a[tid + 512].x * scale;
}

// ---------------- launcher --------------------------------------------------
extern "C" void kernel_launch(void* const* d_in, const int* in_sizes, int n_in,
                              void* d_out, int out_size) {
    const float* x  = (const float*)d_in[0];
    const float* wq = (const float*)d_in[1];
    const float* wk = (const float*)d_in[2];
    const float* wv = (const float*)d_in[3];
    float* out = (float*)d_out;

    init_twiddles<<<1, 512>>>();
    fft_forward<<<NSIG, 512>>>(x);
    qkv_kernel<<<dim3(3, H), 256>>>(wq, wk, wv);
    attn_kernel<<<dim3((F + TR - 1) / TR, H), 256>>>();
    ifft_kernel<<<NSIG, 512>>>(out);
}

// round 7
// speedup vs baseline: 1.1271x; 1.1271x over previous
#include <cuda_runtime.h>
#include <math.h>

#define H 160           // B*G = 4*40 heads
#define C 13
#define T 1024
#define F 513           // rfft bins
#define NSIG (H * C)    // 2080 signals

typedef unsigned long long ull;

// ---------------- f32x2 packed math helpers (sm_103a FFMA2) ----------------
__device__ __forceinline__ ull pk2(float a, float b) {
    ull r;
    asm("mov.b64 %0, {%1, %2};" : "=l"(r) : "r"(__float_as_uint(a)), "r"(__float_as_uint(b)));
    return r;
}
__device__ __forceinline__ void upk2(ull v, float& a, float& b) {
    unsigned lo, hi;
    asm("mov.b64 {%0, %1}, %2;" : "=r"(lo), "=r"(hi) : "l"(v));
    a = __uint_as_float(lo);
    b = __uint_as_float(hi);
}
__device__ __forceinline__ ull fma2(ull a, ull b, ull c) {
    ull d;
    asm("fma.rn.f32x2 %0, %1, %2, %3;" : "=l"(d) : "l"(a), "l"(b), "l"(c));
    return d;
}

// ---------------- scratch (device globals: allowed; no runtime alloc) ------
__device__ float2 d_W[512];        // twiddles exp(-2*pi*i*k/1024)
__device__ float2 d_X[H * C * F];  // spectrum, layout [head][c][f]
__device__ float2 d_Q[H * C * F];
__device__ float2 d_K[H * C * F];
__device__ float2 d_V[H * C * F];
__device__ float2 d_O[H * C * F];

// ---------------- twiddle init (double trig for precision) -----------------
__global__ void init_twiddles() {
    int k = threadIdx.x;  // 0..511
    double ang = -2.0 * 3.14159265358979323846 * (double)k / 1024.0;
    d_W[k] = make_float2((float)cos(ang), (float)sin(ang));
}

// ---------------- shared radix-2 DIT FFT core (1024 pts, 512 threads) ------
__device__ __forceinline__ void fft_stages(float2* a, bool inverse) {
    int tid = threadIdx.x;
#pragma unroll
    for (int s = 1; s <= 10; ++s) {
        __syncthreads();
        int half = 1 << (s - 1);
        int k = tid & (half - 1);
        int i0 = ((tid >> (s - 1)) << s) + k;
        float2 w = d_W[k << (10 - s)];
        if (inverse) w.y = -w.y;
        float2 u = a[i0];
        float2 v = a[i0 + half];
        float tr = w.x * v.x - w.y * v.y;
        float ti = w.x * v.y + w.y * v.x;
        a[i0]        = make_float2(u.x + tr, u.y + ti);
        a[i0 + half] = make_float2(u.x - tr, u.y - ti);
    }
    __syncthreads();
}

// ---------------- forward rfft: x[sig][0..1023] -> d_X[sig][0..512] --------
__global__ void fft_forward(const float* __restrict__ x) {
    __shared__ float2 a[1024];
    int sig = blockIdx.x;   // head*13 + c
    int tid = threadIdx.x;  // 0..511
    const float* xp = x + sig * 1024;
    a[__brev(tid) >> 22]       = make_float2(xp[tid], 0.f);
    a[__brev(tid + 512) >> 22] = make_float2(xp[tid + 512], 0.f);
    fft_stages(a, false);
    float2* Xp = d_X + sig * F;
    Xp[tid] = a[tid];
    if (tid == 0) Xp[512] = a[512];
}

// ---------------- QKV: [head][c][f] = sum_cin X[head][cin][f] * W[cin][c] --
__global__ void qkv_kernel(const float* __restrict__ wq,
                           const float* __restrict__ wk,
                           const float* __restrict__ wv) {
    __shared__ float ws[3][169];
    int tid = threadIdx.x;
    if (tid < 169) {
        ws[0][tid] = wq[tid];
        ws[1][tid] = wk[tid];
        ws[2][tid] = wv[tid];
    }
    __syncthreads();
    int head = blockIdx.y;
    int f = blockIdx.x * blockDim.x + tid;
    if (f >= F) return;
    float xr[13], xi[13];
#pragma unroll
    for (int c = 0; c < 13; ++c) {
        float2 v = d_X[(head * 13 + c) * F + f];
        xr[c] = v.x;
        xi[c] = v.y;
    }
#pragma unroll 1
    for (int co = 0; co < 13; ++co) {
        float qr = 0.f, qi = 0.f, kr = 0.f, ki = 0.f, vr = 0.f, vi = 0.f;
#pragma unroll
        for (int ci = 0; ci < 13; ++ci) {
            float a = ws[0][ci * 13 + co];
            qr = fmaf(xr[ci], a, qr); qi = fmaf(xi[ci], a, qi);
            float b = ws[1][ci * 13 + co];
            kr = fmaf(xr[ci], b, kr); ki = fmaf(xi[ci], b, ki);
            float g = ws[2][ci * 13 + co];
            vr = fmaf(xr[ci], g, vr); vi = fmaf(xi[ci], g, vi);
        }
        int o = (head * 13 + co) * F + f;
        d_Q[o] = make_float2(qr, qi);
        d_K[o] = make_float2(kr, ki);
        d_V[o] = make_float2(vr, vi);
    }
}

// ---------------- attention ------------------------------------------------
// 256 threads = 8 warps; each warp owns 4 query rows (two packed f32x2 pairs).
// Q pre-packed in smem (uniform broadcast LDS), K/V tiles in smem: each
// K/V column load now serves 4 rows. Scores stored packed float4 per warp.
// Pass 2 splits c into halves (7+6) to keep accumulator regs bounded.
#define TRR 32   // rows per CTA
#define KT 128
#define NTILE 5

// dynamic smem layout
#define SM_S_BYTES   (8 * 513 * 16)                 // float4 scores  65664
#define SM_KV_BYTES  (13 * KT * 8)                  // float2 tiles   13312
#define SM_Q_BYTES   (8 * 13 * 4 * 8)               // packed Q        3328
#define SM_TOTAL     (SM_S_BYTES + SM_KV_BYTES + SM_Q_BYTES)  // 82304

__global__ __launch_bounds__(256, 2) void attn_kernel() {
    extern __shared__ char smem_raw[];
    float4* s_sm = (float4*)smem_raw;                          // [w][513]
    float2* kv   = (float2*)(smem_raw + SM_S_BYTES);           // [c][128]
    ull*    qpk  = (ull*)(smem_raw + SM_S_BYTES + SM_KV_BYTES);// [w][13][4]

    int head = blockIdx.y;
    int tid = threadIdx.x, lane = tid & 31, w = tid >> 5;
    int fbase = blockIdx.x * TRR + 4 * w;

    // ---- load + pack Q rows fbase..fbase+3 (lanes 0..12 handle c=lane) ----
    if (lane < 13) {
        const float2* qp = d_Q + (head * 13 + lane) * F + fbase;
        float2 a0 = (fbase + 0 < F) ? qp[0] : make_float2(0.f, 0.f);
        float2 a1 = (fbase + 1 < F) ? qp[1] : make_float2(0.f, 0.f);
        float2 a2 = (fbase + 2 < F) ? qp[2] : make_float2(0.f, 0.f);
        float2 a3 = (fbase + 3 < F) ? qp[3] : make_float2(0.f, 0.f);
        ull* dst = qpk + (w * 13 + lane) * 4;
        dst[0] = pk2(a0.x, a1.x);   // qx01
        dst[1] = pk2(a2.x, a3.x);   // qx23
        dst[2] = pk2(a0.y, a1.y);   // qy01
        dst[3] = pk2(a2.y, a3.y);   // qy23
    }
    __syncwarp();

    const ull Z = pk2(0.f, 0.f);
    float m0 = 0.f, m1 = 0.f, m2 = 0.f, m3 = 0.f;  // scores >= 0

    // ================= pass 1: scores ====================================
    for (int tile = 0; tile < NTILE; ++tile) {
        int base = tile * KT;
        __syncthreads();
        for (int i = tid; i < 13 * KT; i += 256) {
            int c = i >> 7, fl = i & 127, f2 = base + fl;
            kv[i] = (f2 < F) ? d_K[(head * 13 + c) * F + f2] : make_float2(0.f, 0.f);
        }
        __syncthreads();
#pragma unroll
        for (int sb = 0; sb < 2; ++sb) {
            int col0 = base + sb * 64 + lane;   // j=0 column
            int col1 = col0 + 32;               // j=1 column
            ull Aa01 = Z, Aa23 = Z, Ba01 = Z, Ba23 = Z, Sa01 = Z, Sa23 = Z;
            ull Ab01 = Z, Ab23 = Z, Bb01 = Z, Bb23 = Z, Sb01 = Z, Sb23 = Z;
#pragma unroll
            for (int c = 0; c < 13; ++c) {
                const ulonglong2* qq = (const ulonglong2*)(qpk + (w * 13 + c) * 4);
                ulonglong2 t0 = qq[0];  // {qx01, qx23}
                ulonglong2 t1 = qq[1];  // {qy01, qy23}
                float2 k0 = kv[c * KT + sb * 64 + lane];
                float2 k1 = kv[c * KT + sb * 64 + 32 + lane];
                ull kxx = pk2(k0.x, k0.x), kyy = pk2(k0.y, k0.y);
                Aa01 = fma2(t0.x, kxx, Aa01);  Aa23 = fma2(t0.y, kxx, Aa23);
                Ba01 = fma2(t1.x, kyy, Ba01);  Ba23 = fma2(t1.y, kyy, Ba23);
                Sa01 = fma2(t0.x, kyy, Sa01);  Sa01 = fma2(t1.x, kxx, Sa01);
                Sa23 = fma2(t0.y, kyy, Sa23);  Sa23 = fma2(t1.y, kxx, Sa23);
                kxx = pk2(k1.x, k1.x);  kyy = pk2(k1.y, k1.y);
                Ab01 = fma2(t0.x, kxx, Ab01);  Ab23 = fma2(t0.y, kxx, Ab23);
                Bb01 = fma2(t1.x, kyy, Bb01);  Bb23 = fma2(t1.y, kyy, Bb23);
                Sb01 = fma2(t0.x, kyy, Sb01);  Sb01 = fma2(t1.x, kxx, Sb01);
                Sb23 = fma2(t0.y, kyy, Sb23);  Sb23 = fma2(t1.y, kxx, Sb23);
            }
            // epilogue j=0
            {
                float a0, a1, a2, a3, b0, b1, b2, b3, s0, s1, s2, s3;
                upk2(Aa01, a0, a1); upk2(Aa23, a2, a3);
                upk2(Ba01, b0, b1); upk2(Ba23, b2, b3);
                upk2(Sa01, s0, s1); upk2(Sa23, s2, s3);
                float sr0 = a0 - b0, sr1 = a1 - b1, sr2 = a2 - b2, sr3 = a3 - b3;
                float n0 = fmaf(sr0, sr0, s0 * s0);
                float n1 = fmaf(sr1, sr1, s1 * s1);
                float n2 = fmaf(sr2, sr2, s2 * s2);
                float n3 = fmaf(sr3, sr3, s3 * s3);
                float sc0 = n0 > 0.f ? n0 * __frsqrt_rn(n0) : 0.f;
                float sc1 = n1 > 0.f ? n1 * __frsqrt_rn(n1) : 0.f;
                float sc2 = n2 > 0.f ? n2 * __frsqrt_rn(n2) : 0.f;
                float sc3 = n3 > 0.f ? n3 * __frsqrt_rn(n3) : 0.f;
                m0 = fmaxf(m0, sc0); m1 = fmaxf(m1, sc1);
                m2 = fmaxf(m2, sc2); m3 = fmaxf(m3, sc3);
                if (col0 < F) s_sm[w * 513 + col0] = make_float4(sc0, sc1, sc2, sc3);
            }
            // epilogue j=1
            {
                float a0, a1, a2, a3, b0, b1, b2, b3, s0, s1, s2, s3;
                upk2(Ab01, a0, a1); upk2(Ab23, a2, a3);
                upk2(Bb01, b0, b1); upk2(Bb23, b2, b3);
                upk2(Sb01, s0, s1); upk2(Sb23, s2, s3);
                float sr0 = a0 - b0, sr1 = a1 - b1, sr2 = a2 - b2, sr3 = a3 - b3;
                float n0 = fmaf(sr0, sr0, s0 * s0);
                float n1 = fmaf(sr1, sr1, s1 * s1);
                float n2 = fmaf(sr2, sr2, s2 * s2);
                float n3 = fmaf(sr3, sr3, s3 * s3);
                float sc0 = n0 > 0.f ? n0 * __frsqrt_rn(n0) : 0.f;
                float sc1 = n1 > 0.f ? n1 * __frsqrt_rn(n1) : 0.f;
                float sc2 = n2 > 0.f ? n2 * __frsqrt_rn(n2) : 0.f;
                float sc3 = n3 > 0.f ? n3 * __frsqrt_rn(n3) : 0.f;
                m0 = fmaxf(m0, sc0); m1 = fmaxf(m1, sc1);
                m2 = fmaxf(m2, sc2); m3 = fmaxf(m3, sc3);
                if (col1 < F) s_sm[w * 513 + col1] = make_float4(sc0, sc1, sc2, sc3);
            }
        }
    }

    // ================= softmax (warp-local, 4 rows) =======================
#pragma unroll
    for (int o = 16; o; o >>= 1) {
        m0 = fmaxf(m0, __shfl_xor_sync(0xffffffffu, m0, o));
        m1 = fmaxf(m1, __shfl_xor_sync(0xffffffffu, m1, o));
        m2 = fmaxf(m2, __shfl_xor_sync(0xffffffffu, m2, o));
        m3 = fmaxf(m3, __shfl_xor_sync(0xffffffffu, m3, o));
    }
    float l0 = 0.f, l1 = 0.f, l2 = 0.f, l3 = 0.f;
    for (int col = lane; col < F; col += 32) {
        float4 p = s_sm[w * 513 + col];
        p.x = __expf(p.x - m0); p.y = __expf(p.y - m1);
        p.z = __expf(p.z - m2); p.w = __expf(p.w - m3);
        s_sm[w * 513 + col] = p;
        l0 += p.x; l1 += p.y; l2 += p.z; l3 += p.w;
    }
#pragma unroll
    for (int o = 16; o; o >>= 1) {
        l0 += __shfl_xor_sync(0xffffffffu, l0, o);
        l1 += __shfl_xor_sync(0xffffffffu, l1, o);
        l2 += __shfl_xor_sync(0xffffffffu, l2, o);
        l3 += __shfl_xor_sync(0xffffffffu, l3, o);
    }
    float inv0 = 1.f / l0, inv1 = 1.f / l1, inv2 = 1.f / l2, inv3 = 1.f / l3;

    // ================= pass 2: out = P @ V, c split into halves ==========
#pragma unroll 2
    for (int h = 0; h < 2; ++h) {
        const int c0 = h ? 7 : 0;
        const int nc = h ? 6 : 7;
        ull ar01[7], ar23[7], ai01[7], ai23[7];
#pragma unroll
        for (int cc = 0; cc < 7; ++cc) { ar01[cc] = ar23[cc] = ai01[cc] = ai23[cc] = Z; }

        for (int tile = 0; tile < NTILE; ++tile) {
            int base = tile * KT;
            __syncthreads();
            for (int i = tid; i < nc * KT; i += 256) {
                int cc = i >> 7, fl = i & 127, f2 = base + fl;
                kv[i] = (f2 < F) ? d_V[(head * 13 + c0 + cc) * F + f2] : make_float2(0.f, 0.f);
            }
            __syncthreads();
#pragma unroll
            for (int sb = 0; sb < 2; ++sb) {
                int col0 = base + sb * 64 + lane;
                int col1 = col0 + 32;
                float4 pa = (col0 < F) ? s_sm[w * 513 + col0] : make_float4(0.f, 0.f, 0.f, 0.f);
                float4 pb = (col1 < F) ? s_sm[w * 513 + col1] : make_float4(0.f, 0.f, 0.f, 0.f);
                ull p01a = pk2(pa.x, pa.y), p23a = pk2(pa.z, pa.w);
                ull p01b = pk2(pb.x, pb.y), p23b = pk2(pb.z, pb.w);
#pragma unroll
                for (int cc = 0; cc < 7; ++cc) {
                    if (cc < nc) {
                        float2 v0 = kv[cc * KT + sb * 64 + lane];
                        float2 v1 = kv[cc * KT + sb * 64 + 32 + lane];
                        ull vxx = pk2(v0.x, v0.x), vyy = pk2(v0.y, v0.y);
                        ar01[cc] = fma2(p01a, vxx, ar01[cc]);
                        ar23[cc] = fma2(p23a, vxx, ar23[cc]);
                        ai01[cc] = fma2(p01a, vyy, ai01[cc]);
                        ai23[cc] = fma2(p23a, vyy, ai23[cc]);
                        vxx = pk2(v1.x, v1.x); vyy = pk2(v1.y, v1.y);
                        ar01[cc] = fma2(p01b, vxx, ar01[cc]);
                        ar23[cc] = fma2(p23b, vxx, ar23[cc]);
                        ai01[cc] = fma2(p01b, vyy, ai01[cc]);
                        ai23[cc] = fma2(p23b, vyy, ai23[cc]);
                    }
                }
            }
        }
        // reduce + write this half
        for (int cc = 0; cc < nc; ++cc) {
            float r0, r1, r2, r3, i0, i1, i2, i3;
            upk2(ar01[cc], r0, r1); upk2(ar23[cc], r2, r3);
            upk2(ai01[cc], i0, i1); upk2(ai23[cc], i2, i3);
#pragma unroll
            for (int o = 16; o; o >>= 1) {
                r0 += __shfl_xor_sync(0xffffffffu, r0, o);
                r1 += __shfl_xor_sync(0xffffffffu, r1, o);
                r2 += __shfl_xor_sync(0xffffffffu, r2, o);
                r3 += __shfl_xor_sync(0xffffffffu, r3, o);
                i0 += __shfl_xor_sync(0xffffffffu, i0, o);
                i1 += __shfl_xor_sync(0xffffffffu, i1, o);
                i2 += __shfl_xor_sync(0xffffffffu, i2, o);
                i3 += __shfl_xor_sync(0xffffffffu, i3, o);
            }
            if (lane == 0) {
                float2* op = d_O + (head * 13 + c0 + cc) * F + fbase;
                if (fbase + 0 < F) op[0] = make_float2(r0 * inv0, i0 * inv0);
                if (fbase + 1 < F) op[1] = make_float2(r1 * inv1, i1 * inv1);
                if (fbase + 2 < F) op[2] = make_float2(r2 * inv2, i2 * inv2);
                if (fbase + 3 < F) op[3] = make_float2(r3 * inv3, i3 * inv3);
            }
        }
    }
}

// ---------------- irfft: Hermitian extend + inverse FFT, real part ---------
__global__ void ifft_kernel(float* __restrict__ out) {
    __shared__ float2 a[1024];
    int sig = blockIdx.x;
    int tid = threadIdx.x;  // 0..511
    const float2* Op = d_O + sig * F;
    float2 o = Op[tid];
    a[__brev(tid) >> 22] = o;
    if (tid > 0) a[__brev(1024 - tid) >> 22] = make_float2(o.x, -o.y);
    if (tid == 0) a[__brev(512) >> 22] = Op[512];
    fft_stages(a, true);
    const float scale = 1.0f / 1024.0f;
    float* op = out + sig * 1024;
    op[tid]       = a[tid].x * scale;
    op[tid + 512] = a[tid + 512].x * scale;
}

// ---------------- launcher --------------------------------------------------
extern "C" void kernel_launch(void* const* d_in, const int* in_sizes, int n_in,
                              void* d_out, int out_size) {
    const float* x  = (const float*)d_in[0];
    const float* wq = (const float*)d_in[1];
    const float* wk = (const float*)d_in[2];
    const float* wv = (const float*)d_in[3];
    float* out = (float*)d_out;

    cudaFuncSetAttribute(attn_kernel, cudaFuncAttributeMaxDynamicSharedMemorySize, SM_TOTAL);

    init_twiddles<<<1, 512>>>();
    fft_forward<<<NSIG, 512>>>(x);
    qkv_kernel<<<dim3(3, H), 256>>>(wq, wk, wv);
    attn_kernel<<<dim3((F + TRR - 1) / TRR, H), 256, SM_TOTAL>>>();
    ifft_kernel<<<NSIG, 512>>>(out);
}